// round 7
// baseline (speedup 1.0000x reference)
#include <cuda_runtime.h>
#include <cuda_bf16.h>
#include <math.h>
#include <stdint.h>

#define B  64
#define TF 64
#define TE 32
#define H  100
#define E  40
#define SP 256
#define EV 20000
#define M2 (B*TE)
#define NPAD 20096

__device__ float g_h[B*H];
__device__ float g_enc[B*TF*H];
__device__ float g_encA[B*TF*200];
__device__ float g_encS[B*TF*SP];
__device__ float g_sp2m[SP+1];
__device__ float g_dec[B*TE*H];
__device__ float g_rows[M2];
__device__ __nv_bfloat16 g_Ah[M2*128];
__device__ __nv_bfloat16 g_Al[M2*128];
__device__ __nv_bfloat16 g_WhT[NPAD*128];
__device__ __nv_bfloat16 g_WlT[NPAD*128];
// k-major transposed decoder weights
__device__ float dTa [200*100];
__device__ float dTa2[200*100];
__device__ float dTq [200*100];
__device__ float dTw [300*100];
__device__ float dTu [300*100];
__device__ float dTs1[256*100];
__device__ float dTs2[256*100];
__device__ float dTs3[256*100];

__device__ __forceinline__ float sigmoidf_(float x){ return 1.0f/(1.0f+__expf(-x)); }
__device__ __forceinline__ float tanh_fast(float x){ float y; asm("tanh.approx.f32 %0, %1;" : "=f"(y) : "f"(x)); return y; }
__device__ __forceinline__ uint32_t s2u(const void* p){ uint32_t a; asm("{ .reg .u64 t; cvta.to.shared.u64 t, %1; cvt.u32.u64 %0, t; }" : "=r"(a) : "l"(p)); return a; }
__device__ __forceinline__ float4 mixf4(float g, float4 v, float4 r){
    v.x=fmaf(g,v.x-r.x,r.x); v.y=fmaf(g,v.y-r.y,r.y);
    v.z=fmaf(g,v.z-r.z,r.z); v.w=fmaf(g,v.w-r.w,r.w); return v;
}
__device__ __forceinline__ float dot100(const float* __restrict__ w, const float* s){
    const float4* w4=(const float4*)w;
    const float4* s4=(const float4*)s;
    float acc=0.f;
    #pragma unroll
    for(int k=0;k<25;k++){
        float4 a=w4[k], b=s4[k];
        acc+=a.x*b.x+a.y*b.y+a.z*b.z+a.w*b.w;
    }
    return acc;
}
__device__ __forceinline__ void ldm4(uint32_t* r, uint32_t addr){
    asm volatile("ldmatrix.sync.aligned.m8n8.x4.shared.b16 {%0,%1,%2,%3}, [%4];"
      : "=r"(r[0]),"=r"(r[1]),"=r"(r[2]),"=r"(r[3]) : "r"(addr));
}
__device__ __forceinline__ void mma_bf16(float* c, const uint32_t* a, const uint32_t* b){
    asm volatile("mma.sync.aligned.m16n8k16.row.col.f32.bf16.bf16.f32 "
        "{%0,%1,%2,%3}, {%4,%5,%6,%7}, {%8,%9}, {%0,%1,%2,%3};"
        : "+f"(c[0]),"+f"(c[1]),"+f"(c[2]),"+f"(c[3])
        : "r"(a[0]),"r"(a[1]),"r"(a[2]),"r"(a[3]), "r"(b[0]),"r"(b[1]));
}

// ---------------- encoder ----------------
__global__ void k_encoder(const int* __restrict__ enc_in, const float* __restrict__ femb,
                          const float* __restrict__ W, const float* __restrict__ U,
                          const float* __restrict__ bias)
{
    extern __shared__ float sm[];
    float* sW  = sm;
    float* sU  = sW + E*300;
    float* sB  = sU + H*300;
    float* sH  = sB + 600;
    float* sX  = sH + H;
    float* sXs = sX + E;
    float* sHs = sXs + 300;
    int b = blockIdx.x, tid = threadIdx.x, nt = blockDim.x;

    for(int i=tid;i<E*300;i+=nt) sW[i]=W[i];
    for(int i=tid;i<H*300;i+=nt) sU[i]=U[i];
    for(int i=tid;i<600;  i+=nt) sB[i]=bias[i];
    if(tid<H) sH[tid]=0.f;
    __syncthreads();

    for(int t=0;t<TF;t++){
        int tok = enc_in[b*TF+t];
        if(tid<E) sX[tid]=femb[tok*E+tid];
        __syncthreads();
        if(tid<300){
            float a=sB[tid];
            #pragma unroll 8
            for(int k=0;k<E;k++) a += sX[k]*sW[k*300+tid];
            float c=sB[300+tid];
            #pragma unroll 10
            for(int k=0;k<H;k++) c += sH[k]*sU[k*300+tid];
            sXs[tid]=a; sHs[tid]=c;
        }
        __syncthreads();
        if(tid<H){
            float z    = sigmoidf_(sXs[tid]      + sHs[tid]);
            float r    = sigmoidf_(sXs[H+tid]    + sHs[H+tid]);
            float cand = tanhf   (sXs[2*H+tid]  + r*sHs[2*H+tid]);
            float hn   = z*sH[tid] + (1.f-z)*cand;
            sH[tid]=hn;
            g_enc[(b*TF+t)*H+tid]=hn;
        }
        __syncthreads();
    }
    if(tid<H) g_h[b*H+tid]=sH[tid];
}

// ---------------- precompute encA / encS ----------------
__global__ void k_pre(const float* __restrict__ attW1, const float* __restrict__ sp1W)
{
    __shared__ float sE[8*H];
    int r0 = blockIdx.x*8;
    int tid=threadIdx.x;
    for(int i=tid;i<8*H;i+=256) sE[i]=g_enc[r0*H+i];
    __syncthreads();
    for(int idx=tid; idx<8*456; idx+=256){
        int row = idx/456, d = idx-row*456;
        const float* e = sE + row*H;
        float acc=0.f;
        if(d<200){
            #pragma unroll 10
            for(int k=0;k<H;k++) acc += e[k]*attW1[(H+k)*200+d];
            g_encA[(r0+row)*200+d]=acc;
        } else {
            int dd=d-200;
            #pragma unroll 10
            for(int k=0;k<H;k++) acc += e[k]*sp1W[(2*H+k)*SP+dd];
            g_encS[(r0+row)*SP+dd]=acc;
        }
    }
}

__global__ void k_sp2m(const float* __restrict__ sp2W, const float* __restrict__ sp2b)
{
    int k=threadIdx.x;
    float s=0.f;
    for(int j=0;j<SP;j++) s+=sp2W[k*SP+j];
    g_sp2m[k]=s*(1.f/SP);
    if(k==0){
        float t=0.f;
        for(int j=0;j<SP;j++) t+=sp2b[j];
        g_sp2m[SP]=t*(1.f/SP);
    }
}

// ---------------- transpose decoder weights to k-major ----------------
__global__ void k_wtd(const float* __restrict__ attW1, const float* __restrict__ attW2,
                      const float* __restrict__ decW,  const float* __restrict__ decU,
                      const float* __restrict__ sp1W)
{
    int i=blockIdx.x*256+threadIdx.x;
    if(i<200*100){
        int o=i/100, k=i-o*100;
        dTa [o*100+k]=attW1[k*200+o];
        dTa2[o*100+k]=attW1[(100+k)*200+o];
        dTq [o*100+k]=attW2[k*200+o];
    }
    if(i<300*100){
        int o=i/100, k=i-o*100;
        dTw[o*100+k]=decW[k*300+o];
        dTu[o*100+k]=decU[k*300+o];
    }
    if(i<256*100){
        int o=i/100, k=i-o*100;
        dTs1[o*100+k]=sp1W[k*SP+o];
        dTs2[o*100+k]=sp1W[(100+k)*SP+o];
        dTs3[o*100+k]=sp1W[(200+k)*SP+o];
    }
}

// ---------------- W transpose + bf16 hi/lo split ----------------
__global__ void k_wt(const float* __restrict__ W)
{
    __shared__ float tile[100*129];
    int n0=blockIdx.x*128, tid=threadIdx.x;
    for(int i=tid;i<100*128;i+=256){
        int k=i>>7, nl=i&127;
        int n=n0+nl;
        tile[k*129+nl]=(n<EV)?W[k*EV+n]:0.f;
    }
    __syncthreads();
    for(int i=tid;i<128*128;i+=256){
        int nl=i>>7, k=i&127;
        float v=(k<100)?tile[k*129+nl]:0.f;
        __nv_bfloat16 h=__float2bfloat16(v);
        float r=v-__bfloat162float(h);
        int o=(n0+nl)*128+k;
        g_WhT[o]=h; g_WlT[o]=__float2bfloat16(r);
    }
}

// ---------------- decoder ----------------
__global__ void __launch_bounds__(1024,1)
k_decoder(const float* __restrict__ decb, const float* __restrict__ sp1b)
{
    extern __shared__ float sm[];
    float* sEnc   = sm;
    float* sEncA  = sEnc  + TF*H;
    float* sEncS  = sEncA + TF*200;
    float* sH     = sEncS + TF*SP;
    float* sHn    = sH     + H;
    float* sRead  = sHn    + H;
    float* sHbA   = sRead  + H;
    float* sQ     = sHbA   + 200;
    float* sXs    = sQ     + 200;
    float* sHs    = sXs    + 300;
    float* sHrS   = sHs    + 300;
    float* sReadA = sHrS   + SP;
    float* sReadS = sReadA + 200;
    float* sAlpha = sReadS + SP;
    float* sScore = sAlpha + TF;
    float* sG     = sScore + TF;
    float* sSp1b  = sG     + TF;
    float* sSp2m  = sSp1b  + SP;
    float* sDecb  = sSp2m  + SP+1;   // 600

    int b=blockIdx.x, tid=threadIdx.x;
    int lane = tid&31, wid = tid>>5;

    for(int i=tid;i<TF*H;  i+=1024) sEnc[i] =g_enc [b*TF*H+i];
    for(int i=tid;i<TF*200;i+=1024) sEncA[i]=g_encA[b*TF*200+i];
    for(int i=tid;i<TF*SP; i+=1024) sEncS[i]=g_encS[b*TF*SP+i];
    for(int i=tid;i<600;   i+=1024) sDecb[i]=decb[i];
    if(tid<SP)   sSp1b[tid]=sp1b[tid];
    if(tid<SP+1) sSp2m[tid]=g_sp2m[tid];
    if(tid<H)    sH[tid]=g_h[b*H+tid];
    __syncthreads();

    // A0: hbA = h@attW1[0:H], q = h@attW2  (k-major weights, float4)
    if(tid<400){
        if(tid<200) sHbA[tid]=dot100(dTa+tid*100, sH);
        else       { int o=tid-200; sQ[o]=dot100(dTq+o*100, sH); }
    }
    __syncthreads();

    for(int s=0;s<TE;s++){
        // B: scores, float4 LDS + MUFU tanh
        #pragma unroll
        for(int tt=0;tt<2;tt++){
            int t = wid*2+tt;
            const float4* A4=(const float4*)(sEncA+t*200);
            const float4* H4=(const float4*)sHbA;
            const float4* Q4=(const float4*)sQ;
            float p=0.f;
            { int k=lane; float4 a=A4[k],h=H4[k],q=Q4[k];
              p += tanh_fast(h.x+a.x)*q.x + tanh_fast(h.y+a.y)*q.y
                 + tanh_fast(h.z+a.z)*q.z + tanh_fast(h.w+a.w)*q.w; }
            if(lane<18){ int k=lane+32; float4 a=A4[k],h=H4[k],q=Q4[k];
              p += tanh_fast(h.x+a.x)*q.x + tanh_fast(h.y+a.y)*q.y
                 + tanh_fast(h.z+a.z)*q.z + tanh_fast(h.w+a.w)*q.w; }
            #pragma unroll
            for(int o=16;o;o>>=1) p+=__shfl_down_sync(0xffffffffu,p,o);
            if(lane==0) sScore[t]=p;
        }
        __syncthreads();
        // C: softmax over 64 (warp 0)
        if(wid==0){
            float s0=sScore[lane], s1=sScore[32+lane];
            float mx=fmaxf(s0,s1);
            #pragma unroll
            for(int o=16;o;o>>=1) mx=fmaxf(mx,__shfl_xor_sync(0xffffffffu,mx,o));
            float e0=__expf(s0-mx), e1=__expf(s1-mx);
            float su=e0+e1;
            #pragma unroll
            for(int o=16;o;o>>=1) su+=__shfl_xor_sync(0xffffffffu,su,o);
            float inv=1.f/su;
            sAlpha[lane]=e0*inv; sAlpha[32+lane]=e1*inv;
        }
        __syncthreads();
        // D: read = alpha . enc
        if(tid<512){
            int i=tid>>2, ts=tid&3;
            float acc=0.f;
            if(i<H){
                #pragma unroll
                for(int j=0;j<16;j++){ int t=ts*16+j; acc+=sAlpha[t]*sEnc[t*H+i]; }
            }
            acc += __shfl_down_sync(0xffffffffu,acc,2,4);
            acc += __shfl_down_sync(0xffffffffu,acc,1,4);
            if(ts==0 && i<H) sRead[i]=acc;
        }
        __syncthreads();
        // E: GRU matvecs (600) + readA (200), k-major float4
        if(tid<600){
            if(tid<300) sXs[tid]=sDecb[tid]+dot100(dTw+tid*100, sRead);
            else { int u=tid-300; sHs[u]=sDecb[300+u]+dot100(dTu+u*100, sH); }
        } else if(tid<800){
            int d=tid-600;
            sReadA[d]=dot100(dTa2+d*100, sRead);
        }
        __syncthreads();
        // F: GRU pointwise + readS
        if(tid<H){
            float z    = sigmoidf_(sXs[tid]     + sHs[tid]);
            float r    = sigmoidf_(sXs[H+tid]   + sHs[H+tid]);
            float cand = tanhf   (sXs[2*H+tid] + r*sHs[2*H+tid]);
            float hn   = z*sH[tid] + (1.f-z)*cand;
            sHn[tid]=hn;
            g_dec[(b*TE+s)*H+tid]=hn;
        } else if(tid>=128 && tid<384){
            int kk=tid-128;
            sReadS[kk]=dot100(dTs3+kk*100, sRead);
        }
        __syncthreads();
        if(s==TE-1) break;
        // G: hrS (256) + next-step hbA/sQ from hn (400)
        if(tid<256){
            sHrS[tid]=sSp1b[tid]+dot100(dTs1+tid*100, sHn)+dot100(dTs2+tid*100, sRead);
        } else if(tid>=512 && tid<912){
            int o=tid-512;
            if(o<200) sHbA[o]=dot100(dTa+o*100, sHn);
            else { int oo=o-200; sQ[oo]=dot100(dTq+oo*100, sHn); }
        }
        __syncthreads();
        // H: gates, float4
        #pragma unroll
        for(int tt=0;tt<2;tt++){
            int t=wid*2+tt;
            const float4* S4=(const float4*)(sEncS+t*SP);
            const float4* HS4=(const float4*)sHrS;
            const float4* M4=(const float4*)sSp2m;
            float p=0.f;
            #pragma unroll
            for(int j=0;j<2;j++){
                int k=lane+32*j;
                float4 a=S4[k], h=HS4[k], mm=M4[k];
                p += fmaxf(h.x+a.x,0.f)*mm.x + fmaxf(h.y+a.y,0.f)*mm.y
                   + fmaxf(h.z+a.z,0.f)*mm.z + fmaxf(h.w+a.w,0.f)*mm.w;
            }
            #pragma unroll
            for(int o=16;o;o>>=1) p+=__shfl_down_sync(0xffffffffu,p,o);
            if(lane==0) sG[t]=sigmoidf_(p+sSp2m[SP]);
        }
        __syncthreads();
        // I: float4 rewrite, warp-per-2-rows
        {
            int t0=wid*2;
            float g0=sG[t0], g1=sG[t0+1];
            const float4* R4=(const float4*)sRead;
            float4* E4=(float4*)sEnc;
            if(lane<25){
                float4 r=R4[lane];
                E4[t0*25+lane]    = mixf4(g0, E4[t0*25+lane],    r);
                E4[(t0+1)*25+lane]= mixf4(g1, E4[(t0+1)*25+lane],r);
            }
            const float4* RA4=(const float4*)sReadA;
            float4* A4=(float4*)sEncA;
            { int k=lane; float4 r=RA4[k];
              A4[t0*50+k]    =mixf4(g0,A4[t0*50+k],r);
              A4[(t0+1)*50+k]=mixf4(g1,A4[(t0+1)*50+k],r); }
            if(lane<18){ int k=lane+32; float4 r=RA4[k];
              A4[t0*50+k]    =mixf4(g0,A4[t0*50+k],r);
              A4[(t0+1)*50+k]=mixf4(g1,A4[(t0+1)*50+k],r); }
            const float4* RS4=(const float4*)sReadS;
            float4* S4=(float4*)sEncS;
            #pragma unroll
            for(int j=0;j<2;j++){
                int k=lane+32*j; float4 r=RS4[k];
                S4[t0*64+k]    =mixf4(g0,S4[t0*64+k],r);
                S4[(t0+1)*64+k]=mixf4(g1,S4[(t0+1)*64+k],r);
            }
        }
        if(tid<H) sH[tid]=sHn[tid];
        __syncthreads();
    }
}

// ---------------- ff1 + relu -> bf16 hi/lo ----------------
__global__ void k_ff1(const float* __restrict__ W, const float* __restrict__ bias)
{
    __shared__ float sRow[H];
    int m=blockIdx.x, tid=threadIdx.x;
    if(tid<H) sRow[tid]=g_dec[m*H+tid];
    __syncthreads();
    float v=0.f;
    if(tid<H){
        float acc=bias[tid];
        #pragma unroll 10
        for(int k=0;k<H;k++) acc+=sRow[k]*W[k*H+tid];
        v=fmaxf(acc,0.f);
    }
    __nv_bfloat16 h=__float2bfloat16(v);
    float r=v-__bfloat162float(h);
    g_Ah[m*128+tid]=h; g_Al[m*128+tid]=__float2bfloat16(r);
    if(tid==0) g_rows[m]=0.f;
}

// ---------------- HMMA GEMM 64m x 128n, occ 2, fused exp/rowsum ----------------
#define STR 136
#define TBY (STR*2)
#define SOF_AH 1024
#define SOF_AL (SOF_AH + 64*TBY)
#define SOF_WH (SOF_AL + 64*TBY)
#define SOF_WL (SOF_WH + 128*TBY)
#define GSMEM  (SOF_WL + 128*TBY)

__global__ void __launch_bounds__(256,2)
k_gemm(const float* __restrict__ ff2b, float* __restrict__ out)
{
    extern __shared__ char smc[];
    float* sBias=(float*)smc;
    uint32_t sb = s2u(smc);
    int tid=threadIdx.x, wid=tid>>5, lane=tid&31;
    int n0=blockIdx.x*128, m0=blockIdx.y*64;

    if(tid<128) sBias[tid]=(n0+tid<EV)?ff2b[n0+tid]:0.f;

    {
        const uint4* Ah4=(const uint4*)g_Ah;
        const uint4* Al4=(const uint4*)g_Al;
        const uint4* Wh4=(const uint4*)g_WhT;
        const uint4* Wl4=(const uint4*)g_WlT;
        for(int c=tid;c<1024;c+=256){
            int rr=c>>4, kc=c&15;
            uint32_t d = rr*TBY + kc*16;
            *(uint4*)(smc+SOF_AH+d)=Ah4[(m0+rr)*16+kc];
            *(uint4*)(smc+SOF_AL+d)=Al4[(m0+rr)*16+kc];
        }
        for(int c=tid;c<2048;c+=256){
            int rr=c>>4, kc=c&15;
            uint32_t d = rr*TBY + kc*16;
            *(uint4*)(smc+SOF_WH+d)=Wh4[(n0+rr)*16+kc];
            *(uint4*)(smc+SOF_WL+d)=Wl4[(n0+rr)*16+kc];
        }
    }
    __syncthreads();

    int wm=(wid&1)*32, wn=(wid>>1)*32;
    int rA=(lane&7)+((lane>>3)&1)*8, cA=((lane>>4)&1)*8;
    int rB=(lane&7)+((lane>>4)&1)*8, cB=((lane>>3)&1)*8;

    float c[2][4][4];
    #pragma unroll
    for(int i=0;i<2;i++)
        #pragma unroll
        for(int j=0;j<4;j++)
            #pragma unroll
            for(int q=0;q<4;q++) c[i][j][q]=0.f;

    #pragma unroll
    for(int p=0;p<3;p++){
        uint32_t aP = sb + (p==1?SOF_AL:SOF_AH);
        uint32_t bP = sb + (p==2?SOF_WL:SOF_WH);
        uint32_t aBase = aP + (uint32_t)((wm+rA)*STR+cA)*2u;
        uint32_t bBase = bP + (uint32_t)((wn+rB)*STR+cB)*2u;
        #pragma unroll
        for(int k=0;k<8;k++){
            uint32_t a0[4],a1[4];
            ldm4(a0, aBase + k*32u);
            ldm4(a1, aBase + 16u*TBY + k*32u);
            #pragma unroll
            for(int jj=0;jj<2;jj++){
                uint32_t bb[4];
                ldm4(bb, bBase + jj*16u*TBY + k*32u);
                mma_bf16(c[0][jj*2],   a0, bb);
                mma_bf16(c[0][jj*2+1], a0, bb+2);
                mma_bf16(c[1][jj*2],   a1, bb);
                mma_bf16(c[1][jj*2+1], a1, bb+2);
            }
        }
    }

    // epilogue: exp(logit+bias), store, row sums
    #pragma unroll
    for(int mf=0;mf<2;mf++){
        int r0=m0+wm+mf*16+(lane>>2);
        float rs0=0.f, rs1=0.f;
        #pragma unroll
        for(int j=0;j<4;j++){
            int col=n0+wn+j*8+(lane&3)*2;
            int bcol=wn+j*8+(lane&3)*2;
            if(col<EV){
                float2 v0,v1;
                v0.x=__expf(c[mf][j][0]+sBias[bcol]);
                v0.y=__expf(c[mf][j][1]+sBias[bcol+1]);
                v1.x=__expf(c[mf][j][2]+sBias[bcol]);
                v1.y=__expf(c[mf][j][3]+sBias[bcol+1]);
                rs0+=v0.x+v0.y; rs1+=v1.x+v1.y;
                *(float2*)&out[(size_t)r0*EV+col]=v0;
                *(float2*)&out[(size_t)(r0+8)*EV+col]=v1;
            }
        }
        rs0+=__shfl_down_sync(0xffffffffu,rs0,1,4);
        rs0+=__shfl_down_sync(0xffffffffu,rs0,2,4);
        rs1+=__shfl_down_sync(0xffffffffu,rs1,1,4);
        rs1+=__shfl_down_sync(0xffffffffu,rs1,2,4);
        if((lane&3)==0){
            atomicAdd(&g_rows[r0], rs0);
            atomicAdd(&g_rows[r0+8], rs1);
        }
    }
}

// ---------------- normalize ----------------
__global__ void k_norm(float* __restrict__ out)
{
    int row=blockIdx.x, tid=threadIdx.x;
    float inv=1.f/g_rows[row];
    float4* p4=(float4*)(out+(size_t)row*EV);
    for(int j=tid;j<EV/4;j+=256){
        float4 v=p4[j];
        v.x*=inv; v.y*=inv; v.z*=inv; v.w*=inv;
        p4[j]=v;
    }
}

// ---------------- launch ----------------
extern "C" void kernel_launch(void* const* d_in, const int* in_sizes, int n_in,
                              void* d_out, int out_size)
{
    (void)in_sizes; (void)n_in; (void)out_size;
    const int*   enc_in=(const int*)  d_in[0];
    const float* femb  =(const float*)d_in[2];
    const float* encW  =(const float*)d_in[4];
    const float* encU  =(const float*)d_in[5];
    const float* encb  =(const float*)d_in[6];
    const float* decW  =(const float*)d_in[7];
    const float* decU  =(const float*)d_in[8];
    const float* decb  =(const float*)d_in[9];
    const float* attW1 =(const float*)d_in[10];
    const float* attW2 =(const float*)d_in[11];
    const float* sp1W  =(const float*)d_in[12];
    const float* sp1b  =(const float*)d_in[13];
    const float* sp2W  =(const float*)d_in[14];
    const float* sp2b  =(const float*)d_in[15];
    const float* ff1W  =(const float*)d_in[16];
    const float* ff1b  =(const float*)d_in[17];
    const float* ff2W  =(const float*)d_in[18];
    const float* ff2b  =(const float*)d_in[19];
    float* out=(float*)d_out;

    static const int ENC_SMEM = (E*300 + H*300 + 600 + H + E + 300 + 300)*4;
    static const int DEC_SMEM = (TF*H + TF*200 + TF*SP + 3317)*4;

    cudaFuncSetAttribute(k_encoder, cudaFuncAttributeMaxDynamicSharedMemorySize, ENC_SMEM);
    cudaFuncSetAttribute(k_decoder, cudaFuncAttributeMaxDynamicSharedMemorySize, DEC_SMEM);
    cudaFuncSetAttribute(k_gemm,    cudaFuncAttributeMaxDynamicSharedMemorySize, GSMEM);

    k_encoder<<<B,320,ENC_SMEM>>>(enc_in,femb,encW,encU,encb);
    k_pre    <<<(B*TF)/8,256>>>(attW1,sp1W);
    k_sp2m   <<<1,SP>>>(sp2W,sp2b);
    k_wtd    <<<118,256>>>(attW1,attW2,decW,decU,sp1W);
    k_wt     <<<NPAD/128,256>>>(ff2W);
    k_decoder<<<B,1024,DEC_SMEM>>>(decb,sp1b);
    k_ff1    <<<M2,128>>>(ff1W,ff1b);
    k_gemm   <<<dim3(NPAD/128, M2/64),256,GSMEM>>>(ff2b,out);
    k_norm   <<<M2,256>>>(out);
}

// round 8
// speedup vs baseline: 1.1998x; 1.1998x over previous
#include <cuda_runtime.h>
#include <cuda_bf16.h>
#include <math.h>
#include <stdint.h>

#define B  64
#define TF 64
#define TE 32
#define H  100
#define E  40
#define SP 256
#define EV 20000
#define M2 (B*TE)
#define NPAD 20096

__device__ float g_h[B*H];
__device__ float g_enc[B*TF*H];
__device__ float g_encA[B*TF*200];
__device__ float g_encS[B*TF*SP];
__device__ float g_sp2m[SP+1];
__device__ float g_dec[B*TE*H];
__device__ float g_rows[M2];
__device__ __nv_bfloat16 g_Ah[M2*128];
__device__ __nv_bfloat16 g_Al[M2*128];
__device__ __nv_bfloat16 g_WhT[NPAD*128];
__device__ __nv_bfloat16 g_WlT[NPAD*128];

__device__ __forceinline__ float sigmoidf_(float x){ return 1.0f/(1.0f+__expf(-x)); }
__device__ __forceinline__ float tanh_fast(float x){ float y; asm("tanh.approx.f32 %0, %1;" : "=f"(y) : "f"(x)); return y; }
__device__ __forceinline__ uint32_t s2u(const void* p){ uint32_t a; asm("{ .reg .u64 t; cvta.to.shared.u64 t, %1; cvt.u32.u64 %0, t; }" : "=r"(a) : "l"(p)); return a; }
__device__ __forceinline__ float4 mixf4(float g, float4 v, float4 r){
    v.x=fmaf(g,v.x-r.x,r.x); v.y=fmaf(g,v.y-r.y,r.y);
    v.z=fmaf(g,v.z-r.z,r.z); v.w=fmaf(g,v.w-r.w,r.w); return v;
}
// coalesced strided dot: o-major weights, 2 accumulators for ILP/MLP
__device__ __forceinline__ float dots(const float* __restrict__ W, int stride, int o, const float* v){
    float a0=0.f, a1=0.f;
    #pragma unroll
    for(int k=0;k<100;k+=4){
        a0 += v[k]  *W[k*stride+o]     + v[k+1]*W[(k+1)*stride+o];
        a1 += v[k+2]*W[(k+2)*stride+o] + v[k+3]*W[(k+3)*stride+o];
    }
    return a0+a1;
}
__device__ __forceinline__ void ldm4(uint32_t* r, uint32_t addr){
    asm volatile("ldmatrix.sync.aligned.m8n8.x4.shared.b16 {%0,%1,%2,%3}, [%4];"
      : "=r"(r[0]),"=r"(r[1]),"=r"(r[2]),"=r"(r[3]) : "r"(addr));
}
__device__ __forceinline__ void mma_bf16(float* c, const uint32_t* a, const uint32_t* b){
    asm volatile("mma.sync.aligned.m16n8k16.row.col.f32.bf16.bf16.f32 "
        "{%0,%1,%2,%3}, {%4,%5,%6,%7}, {%8,%9}, {%0,%1,%2,%3};"
        : "+f"(c[0]),"+f"(c[1]),"+f"(c[2]),"+f"(c[3])
        : "r"(a[0]),"r"(a[1]),"r"(a[2]),"r"(a[3]), "r"(b[0]),"r"(b[1]));
}

// ---------------- encoder ----------------
__global__ void k_encoder(const int* __restrict__ enc_in, const float* __restrict__ femb,
                          const float* __restrict__ W, const float* __restrict__ U,
                          const float* __restrict__ bias)
{
    extern __shared__ float sm[];
    float* sW  = sm;
    float* sU  = sW + E*300;
    float* sB  = sU + H*300;
    float* sH  = sB + 600;
    float* sX  = sH + H;
    float* sXs = sX + E;
    float* sHs = sXs + 300;
    int b = blockIdx.x, tid = threadIdx.x, nt = blockDim.x;

    for(int i=tid;i<E*300;i+=nt) sW[i]=W[i];
    for(int i=tid;i<H*300;i+=nt) sU[i]=U[i];
    for(int i=tid;i<600;  i+=nt) sB[i]=bias[i];
    if(tid<H) sH[tid]=0.f;
    __syncthreads();

    for(int t=0;t<TF;t++){
        int tok = enc_in[b*TF+t];
        if(tid<E) sX[tid]=femb[tok*E+tid];
        __syncthreads();
        if(tid<300){
            float a=sB[tid];
            #pragma unroll 8
            for(int k=0;k<E;k++) a += sX[k]*sW[k*300+tid];
            float c=sB[300+tid];
            #pragma unroll 10
            for(int k=0;k<H;k++) c += sH[k]*sU[k*300+tid];
            sXs[tid]=a; sHs[tid]=c;
        }
        __syncthreads();
        if(tid<H){
            float z    = sigmoidf_(sXs[tid]      + sHs[tid]);
            float r    = sigmoidf_(sXs[H+tid]    + sHs[H+tid]);
            float cand = tanhf   (sXs[2*H+tid]  + r*sHs[2*H+tid]);
            float hn   = z*sH[tid] + (1.f-z)*cand;
            sH[tid]=hn;
            g_enc[(b*TF+t)*H+tid]=hn;
        }
        __syncthreads();
    }
    if(tid<H) g_h[b*H+tid]=sH[tid];
}

// ---------------- precompute encA / encS ----------------
__global__ void k_pre(const float* __restrict__ attW1, const float* __restrict__ sp1W)
{
    __shared__ float sE[8*H];
    int r0 = blockIdx.x*8;
    int tid=threadIdx.x;
    for(int i=tid;i<8*H;i+=256) sE[i]=g_enc[r0*H+i];
    __syncthreads();
    for(int idx=tid; idx<8*456; idx+=256){
        int row = idx/456, d = idx-row*456;
        const float* e = sE + row*H;
        float acc=0.f;
        if(d<200){
            #pragma unroll 10
            for(int k=0;k<H;k++) acc += e[k]*attW1[(H+k)*200+d];
            g_encA[(r0+row)*200+d]=acc;
        } else {
            int dd=d-200;
            #pragma unroll 10
            for(int k=0;k<H;k++) acc += e[k]*sp1W[(2*H+k)*SP+dd];
            g_encS[(r0+row)*SP+dd]=acc;
        }
    }
}

__global__ void k_sp2m(const float* __restrict__ sp2W, const float* __restrict__ sp2b)
{
    int k=threadIdx.x;
    float s=0.f;
    for(int j=0;j<SP;j++) s+=sp2W[k*SP+j];
    g_sp2m[k]=s*(1.f/SP);
    if(k==0){
        float t=0.f;
        for(int j=0;j<SP;j++) t+=sp2b[j];
        g_sp2m[SP]=t*(1.f/SP);
    }
}

// ---------------- W transpose + bf16 hi/lo split ----------------
__global__ void k_wt(const float* __restrict__ W)
{
    __shared__ float tile[100*129];
    int n0=blockIdx.x*128, tid=threadIdx.x;
    for(int i=tid;i<100*128;i+=256){
        int k=i>>7, nl=i&127;
        int n=n0+nl;
        tile[k*129+nl]=(n<EV)?W[k*EV+n]:0.f;
    }
    __syncthreads();
    for(int i=tid;i<128*128;i+=256){
        int nl=i>>7, k=i&127;
        float v=(k<100)?tile[k*129+nl]:0.f;
        __nv_bfloat16 h=__float2bfloat16(v);
        float r=v-__bfloat162float(h);
        int o=(n0+nl)*128+k;
        g_WhT[o]=h; g_WlT[o]=__float2bfloat16(r);
    }
}

// ---------------- decoder: 2 balanced dot-phases per step ----------------
__global__ void __launch_bounds__(1024,1)
k_decoder(const float* __restrict__ attW1, const float* __restrict__ attW2,
          const float* __restrict__ decW,  const float* __restrict__ decU,
          const float* __restrict__ decb,  const float* __restrict__ sp1W,
          const float* __restrict__ sp1b)
{
    extern __shared__ float sm[];
    float* sEnc   = sm;                  // 6400
    float* sEncA  = sEnc  + TF*H;        // 12800
    float* sEncS  = sEncA + TF*200;      // 16384
    float* sH     = sEncS + TF*SP;       // 100
    float* sHn    = sH     + H;          // 100
    float* sRead  = sHn    + H;          // 100
    float* sHbA   = sRead  + H;          // 200
    float* sQ     = sHbA   + 200;        // 200
    float* sXs    = sQ     + 200;        // 300
    float* sHs    = sXs    + 300;        // 300
    float* sHrS   = sHs    + 300;        // 256
    float* sHrSr  = sHrS   + SP;         // 256  (read-half of hrS)
    float* sReadA = sHrSr  + SP;         // 200
    float* sReadS = sReadA + 200;        // 256
    float* sAlpha = sReadS + SP;         // 64
    float* sScore = sAlpha + TF;         // 64
    float* sG     = sScore + TF;         // 64
    float* sSp1b  = sG     + TF;         // 256
    float* sSp2m  = sSp1b  + SP;         // 257
    float* sDecb  = sSp2m  + SP+1;       // 600

    int b=blockIdx.x, tid=threadIdx.x;
    int lane = tid&31, wid = tid>>5;

    for(int i=tid;i<TF*H;  i+=1024) sEnc[i] =g_enc [b*TF*H+i];
    for(int i=tid;i<TF*200;i+=1024) sEncA[i]=g_encA[b*TF*200+i];
    for(int i=tid;i<TF*SP; i+=1024) sEncS[i]=g_encS[b*TF*SP+i];
    for(int i=tid;i<600;   i+=1024) sDecb[i]=decb[i];
    if(tid<SP)   sSp1b[tid]=sp1b[tid];
    if(tid<SP+1) sSp2m[tid]=g_sp2m[tid];
    if(tid<H)    sH[tid]=g_h[b*H+tid];
    __syncthreads();

    // A0: hbA/q from h0 (400) + decU@h0 -> sHs (300)
    if(tid<400){
        if(tid<200) sHbA[tid]=dots(attW1,200,tid,sH);
        else       { int o=tid-200; sQ[o]=dots(attW2,200,o,sH); }
    } else if(tid<700){
        int u=tid-400;
        sHs[u]=sDecb[300+u]+dots(decU,300,u,sH);
    }
    __syncthreads();

    for(int s=0;s<TE;s++){
        // B: scores, float4 LDS + MUFU tanh
        #pragma unroll
        for(int tt=0;tt<2;tt++){
            int t = wid*2+tt;
            const float4* A4=(const float4*)(sEncA+t*200);
            const float4* H4=(const float4*)sHbA;
            const float4* Q4=(const float4*)sQ;
            float p=0.f;
            { int k=lane; float4 a=A4[k],h=H4[k],q=Q4[k];
              p += tanh_fast(h.x+a.x)*q.x + tanh_fast(h.y+a.y)*q.y
                 + tanh_fast(h.z+a.z)*q.z + tanh_fast(h.w+a.w)*q.w; }
            if(lane<18){ int k=lane+32; float4 a=A4[k],h=H4[k],q=Q4[k];
              p += tanh_fast(h.x+a.x)*q.x + tanh_fast(h.y+a.y)*q.y
                 + tanh_fast(h.z+a.z)*q.z + tanh_fast(h.w+a.w)*q.w; }
            #pragma unroll
            for(int o=16;o;o>>=1) p+=__shfl_down_sync(0xffffffffu,p,o);
            if(lane==0) sScore[t]=p;
        }
        __syncthreads();
        // C: softmax over 64 (warp 0)
        if(wid==0){
            float s0=sScore[lane], s1=sScore[32+lane];
            float mx=fmaxf(s0,s1);
            #pragma unroll
            for(int o=16;o;o>>=1) mx=fmaxf(mx,__shfl_xor_sync(0xffffffffu,mx,o));
            float e0=__expf(s0-mx), e1=__expf(s1-mx);
            float su=e0+e1;
            #pragma unroll
            for(int o=16;o;o>>=1) su+=__shfl_xor_sync(0xffffffffu,su,o);
            float inv=1.f/su;
            sAlpha[lane]=e0*inv; sAlpha[32+lane]=e1*inv;
        }
        __syncthreads();
        // D: read = alpha . enc
        if(tid<512){
            int i=tid>>2, ts=tid&3;
            float acc=0.f;
            if(i<H){
                #pragma unroll
                for(int j=0;j<16;j++){ int t=ts*16+j; acc+=sAlpha[t]*sEnc[t*H+i]; }
            }
            acc += __shfl_down_sync(0xffffffffu,acc,2,4);
            acc += __shfl_down_sync(0xffffffffu,acc,1,4);
            if(ts==0 && i<H) sRead[i]=acc;
        }
        __syncthreads();
        // E: ALL read-dependent dots (1012 lanes x one dot100, coalesced)
        if(tid<300){
            sXs[tid]=sDecb[tid]+dots(decW,300,tid,sRead);
        } else if(tid<500){
            int d=tid-300;
            sReadA[d]=dots(attW1+100*200,200,d,sRead);
        } else if(tid<756){
            int kk=tid-500;
            sReadS[kk]=dots(sp1W+200*SP,SP,kk,sRead);
        } else if(tid<1012){
            int kk=tid-756;
            sHrSr[kk]=dots(sp1W+100*SP,SP,kk,sRead);
        }
        __syncthreads();
        // F: GRU pointwise (sHs precomputed in A0/G)
        if(tid<H){
            float z    = sigmoidf_(sXs[tid]     + sHs[tid]);
            float r    = sigmoidf_(sXs[H+tid]   + sHs[H+tid]);
            float cand = tanhf   (sXs[2*H+tid] + r*sHs[2*H+tid]);
            float hn   = z*sH[tid] + (1.f-z)*cand;
            sHn[tid]=hn;
            g_dec[(b*TE+s)*H+tid]=hn;
        }
        __syncthreads();
        if(s==TE-1) break;
        // G: ALL hn-dependent dots (956 lanes x one dot100)
        if(tid<256){
            sHrS[tid]=sSp1b[tid]+sHrSr[tid]+dots(sp1W,SP,tid,sHn);
        } else if(tid<656){
            int o=tid-256;
            if(o<200) sHbA[o]=dots(attW1,200,o,sHn);
            else { int oo=o-200; sQ[oo]=dots(attW2,200,oo,sHn); }
        } else if(tid<956){
            int u=tid-656;
            sHs[u]=sDecb[300+u]+dots(decU,300,u,sHn);
        }
        __syncthreads();
        // H: gates, float4
        #pragma unroll
        for(int tt=0;tt<2;tt++){
            int t=wid*2+tt;
            const float4* S4=(const float4*)(sEncS+t*SP);
            const float4* HS4=(const float4*)sHrS;
            const float4* M4=(const float4*)sSp2m;
            float p=0.f;
            #pragma unroll
            for(int j=0;j<2;j++){
                int k=lane+32*j;
                float4 a=S4[k], h=HS4[k], mm=M4[k];
                p += fmaxf(h.x+a.x,0.f)*mm.x + fmaxf(h.y+a.y,0.f)*mm.y
                   + fmaxf(h.z+a.z,0.f)*mm.z + fmaxf(h.w+a.w,0.f)*mm.w;
            }
            #pragma unroll
            for(int o=16;o;o>>=1) p+=__shfl_down_sync(0xffffffffu,p,o);
            if(lane==0) sG[t]=sigmoidf_(p+sSp2m[SP]);
        }
        __syncthreads();
        // I: float4 rewrite, warp-per-2-rows
        {
            int t0=wid*2;
            float g0=sG[t0], g1=sG[t0+1];
            const float4* R4=(const float4*)sRead;
            float4* E4=(float4*)sEnc;
            if(lane<25){
                float4 r=R4[lane];
                E4[t0*25+lane]    = mixf4(g0, E4[t0*25+lane],    r);
                E4[(t0+1)*25+lane]= mixf4(g1, E4[(t0+1)*25+lane],r);
            }
            const float4* RA4=(const float4*)sReadA;
            float4* A4=(float4*)sEncA;
            { int k=lane; float4 r=RA4[k];
              A4[t0*50+k]    =mixf4(g0,A4[t0*50+k],r);
              A4[(t0+1)*50+k]=mixf4(g1,A4[(t0+1)*50+k],r); }
            if(lane<18){ int k=lane+32; float4 r=RA4[k];
              A4[t0*50+k]    =mixf4(g0,A4[t0*50+k],r);
              A4[(t0+1)*50+k]=mixf4(g1,A4[(t0+1)*50+k],r); }
            const float4* RS4=(const float4*)sReadS;
            float4* S4=(float4*)sEncS;
            #pragma unroll
            for(int j=0;j<2;j++){
                int k=lane+32*j; float4 r=RS4[k];
                S4[t0*64+k]    =mixf4(g0,S4[t0*64+k],r);
                S4[(t0+1)*64+k]=mixf4(g1,S4[(t0+1)*64+k],r);
            }
        }
        if(tid<H) sH[tid]=sHn[tid];
        __syncthreads();
    }
}

// ---------------- ff1 + relu -> bf16 hi/lo ----------------
__global__ void k_ff1(const float* __restrict__ W, const float* __restrict__ bias)
{
    __shared__ float sRow[H];
    int m=blockIdx.x, tid=threadIdx.x;
    if(tid<H) sRow[tid]=g_dec[m*H+tid];
    __syncthreads();
    float v=0.f;
    if(tid<H){
        float acc=bias[tid];
        #pragma unroll 10
        for(int k=0;k<H;k++) acc+=sRow[k]*W[k*H+tid];
        v=fmaxf(acc,0.f);
    }
    __nv_bfloat16 h=__float2bfloat16(v);
    float r=v-__bfloat162float(h);
    g_Ah[m*128+tid]=h; g_Al[m*128+tid]=__float2bfloat16(r);
    if(tid==0) g_rows[m]=0.f;
}

// ---------------- HMMA GEMM 64m x 128n, occ 2, fused exp/rowsum ----------------
#define STR 136
#define TBY (STR*2)
#define SOF_AH 1024
#define SOF_AL (SOF_AH + 64*TBY)
#define SOF_WH (SOF_AL + 64*TBY)
#define SOF_WL (SOF_WH + 128*TBY)
#define GSMEM  (SOF_WL + 128*TBY)

__global__ void __launch_bounds__(256,2)
k_gemm(const float* __restrict__ ff2b, float* __restrict__ out)
{
    extern __shared__ char smc[];
    float* sBias=(float*)smc;
    uint32_t sb = s2u(smc);
    int tid=threadIdx.x, wid=tid>>5, lane=tid&31;
    int n0=blockIdx.x*128, m0=blockIdx.y*64;

    if(tid<128) sBias[tid]=(n0+tid<EV)?ff2b[n0+tid]:0.f;

    {
        const uint4* Ah4=(const uint4*)g_Ah;
        const uint4* Al4=(const uint4*)g_Al;
        const uint4* Wh4=(const uint4*)g_WhT;
        const uint4* Wl4=(const uint4*)g_WlT;
        for(int c=tid;c<1024;c+=256){
            int rr=c>>4, kc=c&15;
            uint32_t d = rr*TBY + kc*16;
            *(uint4*)(smc+SOF_AH+d)=Ah4[(m0+rr)*16+kc];
            *(uint4*)(smc+SOF_AL+d)=Al4[(m0+rr)*16+kc];
        }
        for(int c=tid;c<2048;c+=256){
            int rr=c>>4, kc=c&15;
            uint32_t d = rr*TBY + kc*16;
            *(uint4*)(smc+SOF_WH+d)=Wh4[(n0+rr)*16+kc];
            *(uint4*)(smc+SOF_WL+d)=Wl4[(n0+rr)*16+kc];
        }
    }
    __syncthreads();

    int wm=(wid&1)*32, wn=(wid>>1)*32;
    int rA=(lane&7)+((lane>>3)&1)*8, cA=((lane>>4)&1)*8;
    int rB=(lane&7)+((lane>>4)&1)*8, cB=((lane>>3)&1)*8;

    float c[2][4][4];
    #pragma unroll
    for(int i=0;i<2;i++)
        #pragma unroll
        for(int j=0;j<4;j++)
            #pragma unroll
            for(int q=0;q<4;q++) c[i][j][q]=0.f;

    #pragma unroll
    for(int p=0;p<3;p++){
        uint32_t aP = sb + (p==1?SOF_AL:SOF_AH);
        uint32_t bP = sb + (p==2?SOF_WL:SOF_WH);
        uint32_t aBase = aP + (uint32_t)((wm+rA)*STR+cA)*2u;
        uint32_t bBase = bP + (uint32_t)((wn+rB)*STR+cB)*2u;
        #pragma unroll
        for(int k=0;k<8;k++){
            uint32_t a0[4],a1[4];
            ldm4(a0, aBase + k*32u);
            ldm4(a1, aBase + 16u*TBY + k*32u);
            #pragma unroll
            for(int jj=0;jj<2;jj++){
                uint32_t bb[4];
                ldm4(bb, bBase + jj*16u*TBY + k*32u);
                mma_bf16(c[0][jj*2],   a0, bb);
                mma_bf16(c[0][jj*2+1], a0, bb+2);
                mma_bf16(c[1][jj*2],   a1, bb);
                mma_bf16(c[1][jj*2+1], a1, bb+2);
            }
        }
    }

    #pragma unroll
    for(int mf=0;mf<2;mf++){
        int r0=m0+wm+mf*16+(lane>>2);
        float rs0=0.f, rs1=0.f;
        #pragma unroll
        for(int j=0;j<4;j++){
            int col=n0+wn+j*8+(lane&3)*2;
            int bcol=wn+j*8+(lane&3)*2;
            if(col<EV){
                float2 v0,v1;
                v0.x=__expf(c[mf][j][0]+sBias[bcol]);
                v0.y=__expf(c[mf][j][1]+sBias[bcol+1]);
                v1.x=__expf(c[mf][j][2]+sBias[bcol]);
                v1.y=__expf(c[mf][j][3]+sBias[bcol+1]);
                rs0+=v0.x+v0.y; rs1+=v1.x+v1.y;
                *(float2*)&out[(size_t)r0*EV+col]=v0;
                *(float2*)&out[(size_t)(r0+8)*EV+col]=v1;
            }
        }
        rs0+=__shfl_down_sync(0xffffffffu,rs0,1,4);
        rs0+=__shfl_down_sync(0xffffffffu,rs0,2,4);
        rs1+=__shfl_down_sync(0xffffffffu,rs1,1,4);
        rs1+=__shfl_down_sync(0xffffffffu,rs1,2,4);
        if((lane&3)==0){
            atomicAdd(&g_rows[r0], rs0);
            atomicAdd(&g_rows[r0+8], rs1);
        }
    }
}

// ---------------- normalize ----------------
__global__ void k_norm(float* __restrict__ out)
{
    int row=blockIdx.x, tid=threadIdx.x;
    float inv=1.f/g_rows[row];
    float4* p4=(float4*)(out+(size_t)row*EV);
    for(int j=tid;j<EV/4;j+=256){
        float4 v=p4[j];
        v.x*=inv; v.y*=inv; v.z*=inv; v.w*=inv;
        p4[j]=v;
    }
}

// ---------------- launch ----------------
extern "C" void kernel_launch(void* const* d_in, const int* in_sizes, int n_in,
                              void* d_out, int out_size)
{
    (void)in_sizes; (void)n_in; (void)out_size;
    const int*   enc_in=(const int*)  d_in[0];
    const float* femb  =(const float*)d_in[2];
    const float* encW  =(const float*)d_in[4];
    const float* encU  =(const float*)d_in[5];
    const float* encb  =(const float*)d_in[6];
    const float* decW  =(const float*)d_in[7];
    const float* decU  =(const float*)d_in[8];
    const float* decb  =(const float*)d_in[9];
    const float* attW1 =(const float*)d_in[10];
    const float* attW2 =(const float*)d_in[11];
    const float* sp1W  =(const float*)d_in[12];
    const float* sp1b  =(const float*)d_in[13];
    const float* sp2W  =(const float*)d_in[14];
    const float* sp2b  =(const float*)d_in[15];
    const float* ff1W  =(const float*)d_in[16];
    const float* ff1b  =(const float*)d_in[17];
    const float* ff2W  =(const float*)d_in[18];
    const float* ff2b  =(const float*)d_in[19];
    float* out=(float*)d_out;

    static const int ENC_SMEM = (E*300 + H*300 + 600 + H + E + 300 + 300)*4;
    static const int DEC_SMEM = (TF*H + TF*200 + TF*SP + 3829)*4;

    cudaFuncSetAttribute(k_encoder, cudaFuncAttributeMaxDynamicSharedMemorySize, ENC_SMEM);
    cudaFuncSetAttribute(k_decoder, cudaFuncAttributeMaxDynamicSharedMemorySize, DEC_SMEM);
    cudaFuncSetAttribute(k_gemm,    cudaFuncAttributeMaxDynamicSharedMemorySize, GSMEM);

    k_encoder<<<B,320,ENC_SMEM>>>(enc_in,femb,encW,encU,encb);
    k_pre    <<<(B*TF)/8,256>>>(attW1,sp1W);
    k_sp2m   <<<1,SP>>>(sp2W,sp2b);
    k_wt     <<<NPAD/128,256>>>(ff2W);
    k_decoder<<<B,1024,DEC_SMEM>>>(attW1,attW2,decW,decU,decb,sp1W,sp1b);
    k_ff1    <<<M2,128>>>(ff1W,ff1b);
    k_gemm   <<<dim3(NPAD/128, M2/64),256,GSMEM>>>(ff2b,out);
    k_norm   <<<M2,256>>>(out);
}

// round 9
// speedup vs baseline: 1.4358x; 1.1967x over previous
#include <cuda_runtime.h>
#include <cuda_bf16.h>
#include <math.h>
#include <stdint.h>

#define B  64
#define TF 64
#define TE 32
#define H  100
#define E  40
#define SP 256
#define EV 20000
#define M2 (B*TE)
#define NPAD 20096

__device__ float g_h[B*H];
__device__ float g_enc[B*TF*H];
__device__ float g_encA[B*TF*200];
__device__ float g_encS[B*TF*SP];
__device__ float g_sp2m[SP+1];
__device__ float g_dec[B*TE*H];
__device__ float g_rows[M2];
__device__ __nv_bfloat16 g_Ah[M2*128];
__device__ __nv_bfloat16 g_Al[M2*128];
__device__ __nv_bfloat16 g_WhT[NPAD*128];
__device__ __nv_bfloat16 g_WlT[NPAD*128];
// packed-k4 decoder weights: pW[k4*Nout+o] = W[4k4..4k4+3][o]
__device__ float4 pTa [25*200];
__device__ float4 pTa2[25*200];
__device__ float4 pTq [25*200];
__device__ float4 pTw [25*300];
__device__ float4 pTu [25*300];
__device__ float4 pTs1[25*256];
__device__ float4 pTs2[25*256];
__device__ float4 pTs3[25*256];

__device__ __forceinline__ float sigmoidf_(float x){ return 1.0f/(1.0f+__expf(-x)); }
__device__ __forceinline__ float tanh_fast(float x){ float y; asm("tanh.approx.f32 %0, %1;" : "=f"(y) : "f"(x)); return y; }
__device__ __forceinline__ uint32_t s2u(const void* p){ uint32_t a; asm("{ .reg .u64 t; cvta.to.shared.u64 t, %1; cvt.u32.u64 %0, t; }" : "=r"(a) : "l"(p)); return a; }
__device__ __forceinline__ float4 mixf4(float g, float4 v, float4 r){
    v.x=fmaf(g,v.x-r.x,r.x); v.y=fmaf(g,v.y-r.y,r.y);
    v.z=fmaf(g,v.z-r.z,r.z); v.w=fmaf(g,v.w-r.w,r.w); return v;
}
// packed dot: 25 x (LDG.128 + LDS.128 + 4 FMA), coalesced across lanes (o contiguous)
__device__ __forceinline__ float dotp(const float4* __restrict__ W, int Nout, int o, const float4* v4){
    float a0=0.f, a1=0.f;
    #pragma unroll
    for(int k=0;k<25;k++){
        float4 w=W[k*Nout+o]; float4 s=v4[k];
        a0 += w.x*s.x + w.y*s.y;
        a1 += w.z*s.z + w.w*s.w;
    }
    return a0+a1;
}
__device__ __forceinline__ void ldm4(uint32_t* r, uint32_t addr){
    asm volatile("ldmatrix.sync.aligned.m8n8.x4.shared.b16 {%0,%1,%2,%3}, [%4];"
      : "=r"(r[0]),"=r"(r[1]),"=r"(r[2]),"=r"(r[3]) : "r"(addr));
}
__device__ __forceinline__ void mma_bf16(float* c, const uint32_t* a, const uint32_t* b){
    asm volatile("mma.sync.aligned.m16n8k16.row.col.f32.bf16.bf16.f32 "
        "{%0,%1,%2,%3}, {%4,%5,%6,%7}, {%8,%9}, {%0,%1,%2,%3};"
        : "+f"(c[0]),"+f"(c[1]),"+f"(c[2]),"+f"(c[3])
        : "r"(a[0]),"r"(a[1]),"r"(a[2]),"r"(a[3]), "r"(b[0]),"r"(b[1]));
}

// ---------------- encoder ----------------
__global__ void k_encoder(const int* __restrict__ enc_in, const float* __restrict__ femb,
                          const float* __restrict__ W, const float* __restrict__ U,
                          const float* __restrict__ bias)
{
    extern __shared__ float sm[];
    float* sW  = sm;
    float* sU  = sW + E*300;
    float* sB  = sU + H*300;
    float* sH  = sB + 600;
    float* sX  = sH + H;
    float* sXs = sX + E;
    float* sHs = sXs + 300;
    int b = blockIdx.x, tid = threadIdx.x, nt = blockDim.x;

    for(int i=tid;i<E*300;i+=nt) sW[i]=W[i];
    for(int i=tid;i<H*300;i+=nt) sU[i]=U[i];
    for(int i=tid;i<600;  i+=nt) sB[i]=bias[i];
    if(tid<H) sH[tid]=0.f;
    __syncthreads();

    for(int t=0;t<TF;t++){
        int tok = enc_in[b*TF+t];
        if(tid<E) sX[tid]=femb[tok*E+tid];
        __syncthreads();
        if(tid<300){
            float a=sB[tid];
            #pragma unroll 8
            for(int k=0;k<E;k++) a += sX[k]*sW[k*300+tid];
            float c=sB[300+tid];
            #pragma unroll 10
            for(int k=0;k<H;k++) c += sH[k]*sU[k*300+tid];
            sXs[tid]=a; sHs[tid]=c;
        }
        __syncthreads();
        if(tid<H){
            float z    = sigmoidf_(sXs[tid]      + sHs[tid]);
            float r    = sigmoidf_(sXs[H+tid]    + sHs[H+tid]);
            float cand = tanhf   (sXs[2*H+tid]  + r*sHs[2*H+tid]);
            float hn   = z*sH[tid] + (1.f-z)*cand;
            sH[tid]=hn;
            g_enc[(b*TF+t)*H+tid]=hn;
        }
        __syncthreads();
    }
    if(tid<H) g_h[b*H+tid]=sH[tid];
}

// ---------------- precompute encA / encS ----------------
__global__ void k_pre(const float* __restrict__ attW1, const float* __restrict__ sp1W)
{
    __shared__ float sE[8*H];
    int r0 = blockIdx.x*8;
    int tid=threadIdx.x;
    for(int i=tid;i<8*H;i+=256) sE[i]=g_enc[r0*H+i];
    __syncthreads();
    for(int idx=tid; idx<8*456; idx+=256){
        int row = idx/456, d = idx-row*456;
        const float* e = sE + row*H;
        float acc=0.f;
        if(d<200){
            #pragma unroll 10
            for(int k=0;k<H;k++) acc += e[k]*attW1[(H+k)*200+d];
            g_encA[(r0+row)*200+d]=acc;
        } else {
            int dd=d-200;
            #pragma unroll 10
            for(int k=0;k<H;k++) acc += e[k]*sp1W[(2*H+k)*SP+dd];
            g_encS[(r0+row)*SP+dd]=acc;
        }
    }
}

__global__ void k_sp2m(const float* __restrict__ sp2W, const float* __restrict__ sp2b)
{
    int k=threadIdx.x;
    float s=0.f;
    for(int j=0;j<SP;j++) s+=sp2W[k*SP+j];
    g_sp2m[k]=s*(1.f/SP);
    if(k==0){
        float t=0.f;
        for(int j=0;j<SP;j++) t+=sp2b[j];
        g_sp2m[SP]=t*(1.f/SP);
    }
}

// ---------------- pack decoder weights to k4-interleaved layout ----------------
__global__ void k_wp(const float* __restrict__ attW1, const float* __restrict__ attW2,
                     const float* __restrict__ decW,  const float* __restrict__ decU,
                     const float* __restrict__ sp1W)
{
    int i=blockIdx.x*256+threadIdx.x;
    if(i<25*200){
        int k4=i/200, o=i-k4*200, k=4*k4;
        pTa [i]=make_float4(attW1[k*200+o],attW1[(k+1)*200+o],attW1[(k+2)*200+o],attW1[(k+3)*200+o]);
        pTa2[i]=make_float4(attW1[(100+k)*200+o],attW1[(101+k)*200+o],attW1[(102+k)*200+o],attW1[(103+k)*200+o]);
        pTq [i]=make_float4(attW2[k*200+o],attW2[(k+1)*200+o],attW2[(k+2)*200+o],attW2[(k+3)*200+o]);
    }
    if(i<25*300){
        int k4=i/300, o=i-k4*300, k=4*k4;
        pTw[i]=make_float4(decW[k*300+o],decW[(k+1)*300+o],decW[(k+2)*300+o],decW[(k+3)*300+o]);
        pTu[i]=make_float4(decU[k*300+o],decU[(k+1)*300+o],decU[(k+2)*300+o],decU[(k+3)*300+o]);
    }
    if(i<25*256){
        int k4=i>>8, o=i&255, k=4*k4;
        pTs1[i]=make_float4(sp1W[k*SP+o],sp1W[(k+1)*SP+o],sp1W[(k+2)*SP+o],sp1W[(k+3)*SP+o]);
        pTs2[i]=make_float4(sp1W[(100+k)*SP+o],sp1W[(101+k)*SP+o],sp1W[(102+k)*SP+o],sp1W[(103+k)*SP+o]);
        pTs3[i]=make_float4(sp1W[(200+k)*SP+o],sp1W[(201+k)*SP+o],sp1W[(202+k)*SP+o],sp1W[(203+k)*SP+o]);
    }
}

// ---------------- W transpose + bf16 hi/lo split ----------------
__global__ void k_wt(const float* __restrict__ W)
{
    __shared__ float tile[100*129];
    int n0=blockIdx.x*128, tid=threadIdx.x;
    for(int i=tid;i<100*128;i+=256){
        int k=i>>7, nl=i&127;
        int n=n0+nl;
        tile[k*129+nl]=(n<EV)?W[k*EV+n]:0.f;
    }
    __syncthreads();
    for(int i=tid;i<128*128;i+=256){
        int nl=i>>7, k=i&127;
        float v=(k<100)?tile[k*129+nl]:0.f;
        __nv_bfloat16 h=__float2bfloat16(v);
        float r=v-__bfloat162float(h);
        int o=(n0+nl)*128+k;
        g_WhT[o]=h; g_WlT[o]=__float2bfloat16(r);
    }
}

// ---------------- decoder: 2 dot-phases per step, packed-k4 weights ----------------
__global__ void __launch_bounds__(1024,1)
k_decoder(const float* __restrict__ decb, const float* __restrict__ sp1b)
{
    extern __shared__ float sm[];
    float* sEnc   = sm;                  // 6400
    float* sEncA  = sEnc  + TF*H;        // 12800
    float* sEncS  = sEncA + TF*200;      // 16384
    float* sH     = sEncS + TF*SP;       // 100
    float* sHn    = sH     + H;          // 100
    float* sRead  = sHn    + H;          // 100
    float* sHbA   = sRead  + H;          // 200
    float* sQ     = sHbA   + 200;        // 200
    float* sXs    = sQ     + 200;        // 300
    float* sHs    = sXs    + 300;        // 300
    float* sHrS   = sHs    + 300;        // 256
    float* sHrSr  = sHrS   + SP;         // 256
    float* sReadA = sHrSr  + SP;         // 200
    float* sReadS = sReadA + 200;        // 256
    float* sAlpha = sReadS + SP;         // 64
    float* sScore = sAlpha + TF;         // 64
    float* sG     = sScore + TF;         // 64
    float* sSp1b  = sG     + TF;         // 256
    float* sSp2m  = sSp1b  + SP;         // 257
    float* sDecb  = sSp2m  + SP+1;       // 600

    int b=blockIdx.x, tid=threadIdx.x;
    int lane = tid&31, wid = tid>>5;

    for(int i=tid;i<TF*H;  i+=1024) sEnc[i] =g_enc [b*TF*H+i];
    for(int i=tid;i<TF*200;i+=1024) sEncA[i]=g_encA[b*TF*200+i];
    for(int i=tid;i<TF*SP; i+=1024) sEncS[i]=g_encS[b*TF*SP+i];
    for(int i=tid;i<600;   i+=1024) sDecb[i]=decb[i];
    if(tid<SP)   sSp1b[tid]=sp1b[tid];
    if(tid<SP+1) sSp2m[tid]=g_sp2m[tid];
    if(tid<H)    sH[tid]=g_h[b*H+tid];
    __syncthreads();

    // A0: hbA/q from h0 + decU@h0 -> sHs
    {
        const float4* H4=(const float4*)sH;
        if(tid<200)      sHbA[tid]=dotp(pTa,200,tid,H4);
        else if(tid<400){ int o=tid-200; sQ[o]=dotp(pTq,200,o,H4); }
        else if(tid<700){ int u=tid-400; sHs[u]=sDecb[300+u]+dotp(pTu,300,u,H4); }
    }
    __syncthreads();

    for(int s=0;s<TE;s++){
        // B: scores, float4 LDS + MUFU tanh
        #pragma unroll
        for(int tt=0;tt<2;tt++){
            int t = wid*2+tt;
            const float4* A4=(const float4*)(sEncA+t*200);
            const float4* H4=(const float4*)sHbA;
            const float4* Q4=(const float4*)sQ;
            float p=0.f;
            { int k=lane; float4 a=A4[k],h=H4[k],q=Q4[k];
              p += tanh_fast(h.x+a.x)*q.x + tanh_fast(h.y+a.y)*q.y
                 + tanh_fast(h.z+a.z)*q.z + tanh_fast(h.w+a.w)*q.w; }
            if(lane<18){ int k=lane+32; float4 a=A4[k],h=H4[k],q=Q4[k];
              p += tanh_fast(h.x+a.x)*q.x + tanh_fast(h.y+a.y)*q.y
                 + tanh_fast(h.z+a.z)*q.z + tanh_fast(h.w+a.w)*q.w; }
            #pragma unroll
            for(int o=16;o;o>>=1) p+=__shfl_down_sync(0xffffffffu,p,o);
            if(lane==0) sScore[t]=p;
        }
        __syncthreads();
        // C: softmax over 64 (warp 0)
        if(wid==0){
            float s0=sScore[lane], s1=sScore[32+lane];
            float mx=fmaxf(s0,s1);
            #pragma unroll
            for(int o=16;o;o>>=1) mx=fmaxf(mx,__shfl_xor_sync(0xffffffffu,mx,o));
            float e0=__expf(s0-mx), e1=__expf(s1-mx);
            float su=e0+e1;
            #pragma unroll
            for(int o=16;o;o>>=1) su+=__shfl_xor_sync(0xffffffffu,su,o);
            float inv=1.f/su;
            sAlpha[lane]=e0*inv; sAlpha[32+lane]=e1*inv;
        }
        __syncthreads();
        // D: read = alpha . enc
        if(tid<512){
            int i=tid>>2, ts=tid&3;
            float acc=0.f;
            if(i<H){
                #pragma unroll
                for(int j=0;j<16;j++){ int t=ts*16+j; acc+=sAlpha[t]*sEnc[t*H+i]; }
            }
            acc += __shfl_down_sync(0xffffffffu,acc,2,4);
            acc += __shfl_down_sync(0xffffffffu,acc,1,4);
            if(ts==0 && i<H) sRead[i]=acc;
        }
        __syncthreads();
        // E: ALL read-dependent dots (packed)
        {
            const float4* R4=(const float4*)sRead;
            if(tid<300)      sXs[tid]=sDecb[tid]+dotp(pTw,300,tid,R4);
            else if(tid<500){ int d=tid-300; sReadA[d]=dotp(pTa2,200,d,R4); }
            else if(tid<756){ int kk=tid-500; sReadS[kk]=dotp(pTs3,256,kk,R4); }
            else if(tid<1012){ int kk=tid-756; sHrSr[kk]=dotp(pTs2,256,kk,R4); }
        }
        __syncthreads();
        // F: GRU pointwise (sHs precomputed in A0/G)
        if(tid<H){
            float z    = sigmoidf_(sXs[tid]     + sHs[tid]);
            float r    = sigmoidf_(sXs[H+tid]   + sHs[H+tid]);
            float cand = tanhf   (sXs[2*H+tid] + r*sHs[2*H+tid]);
            float hn   = z*sH[tid] + (1.f-z)*cand;
            sHn[tid]=hn;
            g_dec[(b*TE+s)*H+tid]=hn;
        }
        __syncthreads();
        if(s==TE-1) break;
        // G: ALL hn-dependent dots (packed)
        {
            const float4* N4=(const float4*)sHn;
            if(tid<256)      sHrS[tid]=sSp1b[tid]+sHrSr[tid]+dotp(pTs1,256,tid,N4);
            else if(tid<456){ int o=tid-256; sHbA[o]=dotp(pTa,200,o,N4); }
            else if(tid<656){ int o=tid-456; sQ[o]=dotp(pTq,200,o,N4); }
            else if(tid<956){ int u=tid-656; sHs[u]=sDecb[300+u]+dotp(pTu,300,u,N4); }
        }
        __syncthreads();
        // H: gates, float4
        #pragma unroll
        for(int tt=0;tt<2;tt++){
            int t=wid*2+tt;
            const float4* S4=(const float4*)(sEncS+t*SP);
            const float4* HS4=(const float4*)sHrS;
            const float4* M4=(const float4*)sSp2m;
            float p=0.f;
            #pragma unroll
            for(int j=0;j<2;j++){
                int k=lane+32*j;
                float4 a=S4[k], h=HS4[k], mm=M4[k];
                p += fmaxf(h.x+a.x,0.f)*mm.x + fmaxf(h.y+a.y,0.f)*mm.y
                   + fmaxf(h.z+a.z,0.f)*mm.z + fmaxf(h.w+a.w,0.f)*mm.w;
            }
            #pragma unroll
            for(int o=16;o;o>>=1) p+=__shfl_down_sync(0xffffffffu,p,o);
            if(lane==0) sG[t]=sigmoidf_(p+sSp2m[SP]);
        }
        __syncthreads();
        // I: float4 rewrite, warp-per-2-rows
        {
            int t0=wid*2;
            float g0=sG[t0], g1=sG[t0+1];
            const float4* R4=(const float4*)sRead;
            float4* E4=(float4*)sEnc;
            if(lane<25){
                float4 r=R4[lane];
                E4[t0*25+lane]    = mixf4(g0, E4[t0*25+lane],    r);
                E4[(t0+1)*25+lane]= mixf4(g1, E4[(t0+1)*25+lane],r);
            }
            const float4* RA4=(const float4*)sReadA;
            float4* A4=(float4*)sEncA;
            { int k=lane; float4 r=RA4[k];
              A4[t0*50+k]    =mixf4(g0,A4[t0*50+k],r);
              A4[(t0+1)*50+k]=mixf4(g1,A4[(t0+1)*50+k],r); }
            if(lane<18){ int k=lane+32; float4 r=RA4[k];
              A4[t0*50+k]    =mixf4(g0,A4[t0*50+k],r);
              A4[(t0+1)*50+k]=mixf4(g1,A4[(t0+1)*50+k],r); }
            const float4* RS4=(const float4*)sReadS;
            float4* S4=(float4*)sEncS;
            #pragma unroll
            for(int j=0;j<2;j++){
                int k=lane+32*j; float4 r=RS4[k];
                S4[t0*64+k]    =mixf4(g0,S4[t0*64+k],r);
                S4[(t0+1)*64+k]=mixf4(g1,S4[(t0+1)*64+k],r);
            }
        }
        if(tid<H) sH[tid]=sHn[tid];
        __syncthreads();
    }
}

// ---------------- ff1 + relu -> bf16 hi/lo ----------------
__global__ void k_ff1(const float* __restrict__ W, const float* __restrict__ bias)
{
    __shared__ float sRow[H];
    int m=blockIdx.x, tid=threadIdx.x;
    if(tid<H) sRow[tid]=g_dec[m*H+tid];
    __syncthreads();
    float v=0.f;
    if(tid<H){
        float acc=bias[tid];
        #pragma unroll 10
        for(int k=0;k<H;k++) acc+=sRow[k]*W[k*H+tid];
        v=fmaxf(acc,0.f);
    }
    __nv_bfloat16 h=__float2bfloat16(v);
    float r=v-__bfloat162float(h);
    g_Ah[m*128+tid]=h; g_Al[m*128+tid]=__float2bfloat16(r);
    if(tid==0) g_rows[m]=0.f;
}

// ---------------- HMMA GEMM 128m x 128n (R5 proven config), fused exp/rowsum ----------------
#define STR 136
#define TBY (STR*2)
#define SOF_AH 1024
#define SOF_AL (SOF_AH + 128*TBY)
#define SOF_WH (SOF_AL + 128*TBY)
#define SOF_WL (SOF_WH + 128*TBY)
#define GSMEM  (SOF_WL + 128*TBY)

__global__ void __launch_bounds__(256,1)
k_gemm(const float* __restrict__ ff2b, float* __restrict__ out)
{
    extern __shared__ char smc[];
    float* sBias=(float*)smc;
    uint32_t sb = s2u(smc);
    int tid=threadIdx.x, wid=tid>>5, lane=tid&31;
    int n0=blockIdx.x*128, m0=blockIdx.y*128;

    if(tid<128) sBias[tid]=(n0+tid<EV)?ff2b[n0+tid]:0.f;

    {
        const uint4* Ah4=(const uint4*)g_Ah;
        const uint4* Al4=(const uint4*)g_Al;
        const uint4* Wh4=(const uint4*)g_WhT;
        const uint4* Wl4=(const uint4*)g_WlT;
        for(int c=tid;c<2048;c+=256){
            int rr=c>>4, kc=c&15;
            uint32_t d = rr*TBY + kc*16;
            *(uint4*)(smc+SOF_AH+d)=Ah4[(m0+rr)*16+kc];
            *(uint4*)(smc+SOF_AL+d)=Al4[(m0+rr)*16+kc];
            *(uint4*)(smc+SOF_WH+d)=Wh4[(n0+rr)*16+kc];
            *(uint4*)(smc+SOF_WL+d)=Wl4[(n0+rr)*16+kc];
        }
    }
    __syncthreads();

    int wm=(wid>>1)*32, wn=(wid&1)*64;
    int rA=(lane&7)+((lane>>3)&1)*8, cA=((lane>>4)&1)*8;
    int rB=(lane&7)+((lane>>4)&1)*8, cB=((lane>>3)&1)*8;

    float c[2][8][4];
    #pragma unroll
    for(int i=0;i<2;i++)
        #pragma unroll
        for(int j=0;j<8;j++)
            #pragma unroll
            for(int q=0;q<4;q++) c[i][j][q]=0.f;

    #pragma unroll
    for(int p=0;p<3;p++){
        uint32_t aP = sb + (p==1?SOF_AL:SOF_AH);
        uint32_t bP = sb + (p==2?SOF_WL:SOF_WH);
        uint32_t aBase = aP + (uint32_t)((wm+rA)*STR+cA)*2u;
        uint32_t bBase = bP + (uint32_t)((wn+rB)*STR+cB)*2u;
        #pragma unroll
        for(int k=0;k<8;k++){
            uint32_t a0[4],a1[4];
            ldm4(a0, aBase + k*32u);
            ldm4(a1, aBase + 16u*TBY + k*32u);
            #pragma unroll
            for(int jj=0;jj<4;jj++){
                uint32_t bb[4];
                ldm4(bb, bBase + jj*16u*TBY + k*32u);
                mma_bf16(c[0][jj*2],   a0, bb);
                mma_bf16(c[0][jj*2+1], a0, bb+2);
                mma_bf16(c[1][jj*2],   a1, bb);
                mma_bf16(c[1][jj*2+1], a1, bb+2);
            }
        }
    }

    #pragma unroll
    for(int mf=0;mf<2;mf++){
        int r0=m0+wm+mf*16+(lane>>2);
        float rs0=0.f, rs1=0.f;
        #pragma unroll
        for(int j=0;j<8;j++){
            int col=n0+wn+j*8+(lane&3)*2;
            int bcol=wn+j*8+(lane&3)*2;
            if(col<EV){
                float2 v0,v1;
                v0.x=__expf(c[mf][j][0]+sBias[bcol]);
                v0.y=__expf(c[mf][j][1]+sBias[bcol+1]);
                v1.x=__expf(c[mf][j][2]+sBias[bcol]);
                v1.y=__expf(c[mf][j][3]+sBias[bcol+1]);
                rs0+=v0.x+v0.y; rs1+=v1.x+v1.y;
                *(float2*)&out[(size_t)r0*EV+col]=v0;
                *(float2*)&out[(size_t)(r0+8)*EV+col]=v1;
            }
        }
        rs0+=__shfl_down_sync(0xffffffffu,rs0,1,4);
        rs0+=__shfl_down_sync(0xffffffffu,rs0,2,4);
        rs1+=__shfl_down_sync(0xffffffffu,rs1,1,4);
        rs1+=__shfl_down_sync(0xffffffffu,rs1,2,4);
        if((lane&3)==0){
            atomicAdd(&g_rows[r0], rs0);
            atomicAdd(&g_rows[r0+8], rs1);
        }
    }
}

// ---------------- normalize ----------------
__global__ void k_norm(float* __restrict__ out)
{
    int row=blockIdx.x, tid=threadIdx.x;
    float inv=1.f/g_rows[row];
    float4* p4=(float4*)(out+(size_t)row*EV);
    for(int j=tid;j<EV/4;j+=256){
        float4 v=p4[j];
        v.x*=inv; v.y*=inv; v.z*=inv; v.w*=inv;
        p4[j]=v;
    }
}

// ---------------- launch ----------------
extern "C" void kernel_launch(void* const* d_in, const int* in_sizes, int n_in,
                              void* d_out, int out_size)
{
    (void)in_sizes; (void)n_in; (void)out_size;
    const int*   enc_in=(const int*)  d_in[0];
    const float* femb  =(const float*)d_in[2];
    const float* encW  =(const float*)d_in[4];
    const float* encU  =(const float*)d_in[5];
    const float* encb  =(const float*)d_in[6];
    const float* decW  =(const float*)d_in[7];
    const float* decU  =(const float*)d_in[8];
    const float* decb  =(const float*)d_in[9];
    const float* attW1 =(const float*)d_in[10];
    const float* attW2 =(const float*)d_in[11];
    const float* sp1W  =(const float*)d_in[12];
    const float* sp1b  =(const float*)d_in[13];
    const float* sp2W  =(const float*)d_in[14];
    const float* sp2b  =(const float*)d_in[15];
    const float* ff1W  =(const float*)d_in[16];
    const float* ff1b  =(const float*)d_in[17];
    const float* ff2W  =(const float*)d_in[18];
    const float* ff2b  =(const float*)d_in[19];
    float* out=(float*)d_out;

    static const int ENC_SMEM = (E*300 + H*300 + 600 + H + E + 300 + 300)*4;
    static const int DEC_SMEM = (TF*H + TF*200 + TF*SP + 3829)*4;

    cudaFuncSetAttribute(k_encoder, cudaFuncAttributeMaxDynamicSharedMemorySize, ENC_SMEM);
    cudaFuncSetAttribute(k_decoder, cudaFuncAttributeMaxDynamicSharedMemorySize, DEC_SMEM);
    cudaFuncSetAttribute(k_gemm,    cudaFuncAttributeMaxDynamicSharedMemorySize, GSMEM);

    k_encoder<<<B,320,ENC_SMEM>>>(enc_in,femb,encW,encU,encb);
    k_pre    <<<(B*TF)/8,256>>>(attW1,sp1W);
    k_sp2m   <<<1,SP>>>(sp2W,sp2b);
    k_wp     <<<30,256>>>(attW1,attW2,decW,decU,sp1W);
    k_wt     <<<NPAD/128,256>>>(ff2W);
    k_decoder<<<B,1024,DEC_SMEM>>>(decb,sp1b);
    k_ff1    <<<M2,128>>>(ff1W,ff1b);
    k_gemm   <<<dim3(NPAD/128, M2/128),256,GSMEM>>>(ff2b,out);
    k_norm   <<<M2,256>>>(out);
}